// round 17
// baseline (speedup 1.0000x reference)
#include <cuda_runtime.h>
#include <cuda_fp16.h>
#include <math.h>
#include <stdint.h>

// Problem constants
#define SEQ    2048
#define HID    2048
#define NH     32
#define NOPE   128
#define ROPE_D 64
#define QKD    192
#define VD     128
#define KV_RANK 512
#define SWIN   128
#define CKV_W  576
#define KV_W   8192
#define QW     6144
#define AOW    4096
#define NEGINF (-1000000000.0f)
#define ATTN_SCALE 0.07216878364870323f   // 192^-0.5

// ---------------- scratch (device globals; no allocation allowed) ----------------
__device__ float g_q[(size_t)SEQ * QW];
__device__ float g_ckv[(size_t)SEQ * CKV_W];
__device__ float g_kv[(size_t)SEQ * KV_W];
__device__ float g_krope[(size_t)SEQ * ROPE_D];

// fp16 buffers
__device__ __half g_ah[(size_t)SEQ * 4096];          // activations, max K=4096
__device__ __half g_wqh[(size_t)HID * QW];
__device__ __half g_wkvah[(size_t)HID * CKV_W];
__device__ __half g_wkvbh[(size_t)KV_RANK * KV_W];
__device__ __half g_woh[(size_t)AOW * HID];

// ---------------- converts ----------------
__global__ void cvt_act(const float* __restrict__ X, __half* __restrict__ Y,
                        int ldx, int K)
{
    int i = blockIdx.x * blockDim.x + threadIdx.x;
    int kq = K >> 2;
    int row = i / kq;
    int c4  = (i - row * kq) * 4;
    float4 v = *reinterpret_cast<const float4*>(&X[(size_t)row * ldx + c4]);
    __half h[4] = {__float2half_rn(v.x), __float2half_rn(v.y),
                   __float2half_rn(v.z), __float2half_rn(v.w)};
    *reinterpret_cast<uint2*>(&Y[(size_t)row * K + c4]) = *reinterpret_cast<uint2*>(h);
}

__global__ void cvt_wgt(const float* __restrict__ X, __half* __restrict__ Y)
{
    size_t i = ((size_t)blockIdx.x * blockDim.x + threadIdx.x) * 4;
    float4 v = *reinterpret_cast<const float4*>(&X[i]);
    __half h[4] = {__float2half_rn(v.x), __float2half_rn(v.y),
                   __float2half_rn(v.z), __float2half_rn(v.w)};
    *reinterpret_cast<uint2*>(&Y[i]) = *reinterpret_cast<uint2*>(h);
}

// ---------------- mma / ldmatrix wrappers ----------------
__device__ __forceinline__ void mma16816(float* c, const uint32_t* a, const uint32_t* b)
{
    asm volatile(
        "mma.sync.aligned.m16n8k16.row.col.f32.f16.f16.f32 "
        "{%0,%1,%2,%3}, {%4,%5,%6,%7}, {%8,%9}, {%0,%1,%2,%3};\n"
        : "+f"(c[0]), "+f"(c[1]), "+f"(c[2]), "+f"(c[3])
        : "r"(a[0]), "r"(a[1]), "r"(a[2]), "r"(a[3]),
          "r"(b[0]), "r"(b[1]));
}
__device__ __forceinline__ void ldsm4(uint32_t* r, uint32_t addr)
{
    asm volatile("ldmatrix.sync.aligned.m8n8.x4.shared.b16 {%0,%1,%2,%3}, [%4];"
                 : "=r"(r[0]), "=r"(r[1]), "=r"(r[2]), "=r"(r[3]) : "r"(addr));
}
__device__ __forceinline__ void ldsm4t(uint32_t* r, uint32_t addr)
{
    asm volatile("ldmatrix.sync.aligned.m8n8.x4.trans.shared.b16 {%0,%1,%2,%3}, [%4];"
                 : "=r"(r[0]), "=r"(r[1]), "=r"(r[2]), "=r"(r[3]) : "r"(addr));
}
__device__ __forceinline__ void cp16(uint32_t dst, const void* src, int bytes)
{
    asm volatile("cp.async.cg.shared.global [%0], [%1], 16, %2;"
                 :: "r"(dst), "l"(src), "r"(bytes));
}

// ---------------- fp16 single-pass tensor GEMM, BK=64 ----------------
// C[2048, N] = A@B (+bias).  A: [M,K] fp16; B: [K,N] fp16.
// Block 128x128, BK=64, 256 thr, 8 warps (2m x 4n), 3-stage cp.async, 2 CTAs/SM.
#define APAD 72                                  // halves per A smem row (64 + 8 pad)
#define AH_OFF 0
#define BH_OFF (128 * APAD)                      // 9216 halves
#define STG    (128 * APAD + 64 * 128)           // 17408 halves per stage
#define NSTAGES 3
#define GEMM_SMEM (NSTAGES * STG * 2)            // 104448 bytes

__global__ __launch_bounds__(256, 2) void gemm_h(
    const __half* __restrict__ A,
    const __half* __restrict__ B,
    const float* __restrict__ bias,
    float* __restrict__ C, int ldc,
    int N, int K)
{
    extern __shared__ __half dynsmem[];

    const int tid  = threadIdx.x;
    const int lane = tid & 31;
    const int w    = tid >> 5;
    const int wm   = w >> 2;
    const int wn   = w & 3;
    const int bm   = blockIdx.y * 128;
    const int bn   = blockIdx.x * 128;

    uint32_t sbase = (uint32_t)__cvta_generic_to_shared(dynsmem);

    float acc[4][4][4];
    #pragma unroll
    for (int mi = 0; mi < 4; mi++)
        #pragma unroll
        for (int ni = 0; ni < 4; ni++)
            #pragma unroll
            for (int e = 0; e < 4; e++) acc[mi][ni][e] = 0.0f;

    const int nk = K / 64;

    auto issue = [&](int chunk) {
        if (chunk < nk) {
            int kk = chunk * 64;
            uint32_t st = sbase + (chunk % NSTAGES) * STG * 2;
            // A tile: 128 rows x 64 halves (8 x 16B chunks) = 1024 cp16 -> 4/thread
            #pragma unroll
            for (int it = 0; it < 4; it++) {
                int lin = tid + it * 256;
                int m = lin >> 3, c = lin & 7;
                size_t off = (size_t)(bm + m) * K + kk + c * 8;
                cp16(st + AH_OFF * 2 + (m * APAD + c * 8) * 2, A + off, 16);
            }
            // B tile: 64 rows x 128 halves (16 x 16B chunks) = 1024 cp16 -> 4/thread
            #pragma unroll
            for (int it = 0; it < 4; it++) {
                int lin = tid + it * 256;
                int k = lin >> 4, c = lin & 15;
                int col = bn + c * 8;
                int pred = (col + 8 <= N) ? 16 : 0;
                size_t off = (size_t)(kk + k) * N + col;
                int phys = c ^ (k & 7);
                cp16(st + BH_OFF * 2 + (k * 128 + phys * 8) * 2, B + off, pred);
            }
        }
        asm volatile("cp.async.commit_group;");   // always commit (empty tail groups)
    };

    issue(0);
    issue(1);

    for (int ch = 0; ch < nk; ch++) {
        uint32_t stb = sbase + (ch % NSTAGES) * STG * 2;
        asm volatile("cp.async.wait_group %0;" :: "n"(NSTAGES - 2));
        __syncthreads();   // chunk ch visible; all prior-stage reads complete

        issue(ch + 2);

        #pragma unroll
        for (int ks = 0; ks < 4; ks++) {
            int koff = ks * 16 + (lane >> 4) * 8;
            int krow = ks * 16 + (lane & 15);
            int arow = wm * 64 + (lane & 15);

            uint32_t bh[4][2];
            #pragma unroll
            for (int bt = 0; bt < 2; bt++) {
                int cL = wn * 4 + bt * 2 + (lane >> 4);
                int phys = cL ^ (krow & 7);
                uint32_t r[4];
                ldsm4t(r, stb + BH_OFF * 2 + (krow * 128 + phys * 8) * 2);
                bh[bt * 2][0] = r[0]; bh[bt * 2][1] = r[1];
                bh[bt * 2 + 1][0] = r[2]; bh[bt * 2 + 1][1] = r[3];
            }

            uint32_t af[4][4];
            #pragma unroll
            for (int mt = 0; mt < 4; mt++)
                ldsm4(af[mt], stb + AH_OFF * 2 + ((arow + mt * 16) * APAD + koff) * 2);
            #pragma unroll
            for (int mt = 0; mt < 4; mt++)
                #pragma unroll
                for (int nt = 0; nt < 4; nt++)
                    mma16816(acc[mt][nt], af[mt], bh[nt]);
        }
    }

    // ---- store ----
    const int g  = lane >> 2;
    const int q4 = (lane & 3) * 2;
    #pragma unroll
    for (int mi = 0; mi < 4; mi++) {
        int r0 = bm + wm * 64 + mi * 16 + g;
        #pragma unroll
        for (int ni = 0; ni < 4; ni++) {
            int c = bn + wn * 32 + ni * 8 + q4;
            if (c < N) {
                float b0 = bias ? bias[c] : 0.0f;
                float b1 = bias ? bias[c + 1] : 0.0f;
                C[(size_t)r0 * ldc + c]           = acc[mi][ni][0] + b0;
                C[(size_t)r0 * ldc + c + 1]       = acc[mi][ni][1] + b1;
                C[(size_t)(r0 + 8) * ldc + c]     = acc[mi][ni][2] + b0;
                C[(size_t)(r0 + 8) * ldc + c + 1] = acc[mi][ni][3] + b1;
            }
        }
    }
}

// ---------------- RoPE kernels ----------------
__global__ void rope_q_kernel(const float* __restrict__ cosp,
                              const float* __restrict__ sinp)
{
    int idx = blockIdx.x * blockDim.x + threadIdx.x;
    int r = idx & 31;
    int h = (idx >> 5) & 31;
    int i = idx >> 10;
    float* base = &g_q[(size_t)i * QW + h * QKD + NOPE];
    float x0 = base[r];
    float x1 = base[r + 32];
    float c0 = cosp[i * ROPE_D + r];
    float c1 = cosp[i * ROPE_D + 32 + r];
    float s0 = sinp[i * ROPE_D + r];
    float s1 = sinp[i * ROPE_D + 32 + r];
    base[r]      = x0 * c0 - x1 * s0;
    base[r + 32] = x1 * c1 + x0 * s1;
}

__global__ void rope_k_kernel(const float* __restrict__ cosp,
                              const float* __restrict__ sinp)
{
    int idx = blockIdx.x * blockDim.x + threadIdx.x;
    int r = idx & 31;
    int i = idx >> 5;
    const float* base = &g_ckv[(size_t)i * CKV_W + KV_RANK];
    float x0 = base[r];
    float x1 = base[r + 32];
    float c0 = cosp[i * ROPE_D + r];
    float c1 = cosp[i * ROPE_D + 32 + r];
    float s0 = sinp[i * ROPE_D + r];
    float s1 = sinp[i * ROPE_D + 32 + r];
    g_krope[(size_t)i * ROPE_D + r]      = x0 * c0 - x1 * s0;
    g_krope[(size_t)i * ROPE_D + 32 + r] = x1 * c1 + x0 * s1;
}

// ---------------- query-tiled sliding-window attention with sink ----------------
// Output written directly as fp16 into g_ah (consumed by the O-projection GEMM).
#define QT   16
#define QPAD 196
#define KPAD 196
#define VPAD 132
#define LW   144
__global__ __launch_bounds__(256) void attn_tile_kernel(const float* __restrict__ sinks)
{
    __shared__ float Qs[QT][QPAD];
    __shared__ float Ks[16][KPAD];
    __shared__ float Ls[QT][LW];
    __shared__ float Vs[16][VPAD];

    const int i0    = blockIdx.x * QT;
    const int h     = blockIdx.y;
    const int tid   = threadIdx.x;
    const int jbase = i0 - 127;

    #pragma unroll
    for (int it = 0; it < 3; it++) {
        int lin = tid + it * 256;
        int r   = lin / 48;
        int c4  = (lin % 48) * 4;
        float4 v = *reinterpret_cast<const float4*>(
            &g_q[(size_t)(i0 + r) * QW + h * QKD + c4]);
        *reinterpret_cast<float4*>(&Qs[r][c4]) = v;
    }
    __syncthreads();

    const int q = tid >> 4;
    const int j = tid & 15;

    for (int c = 0; c < 9; c++) {
        #pragma unroll
        for (int it = 0; it < 3; it++) {
            int lin = tid + it * 256;
            int r   = lin / 48;
            int c4  = (lin % 48) * 4;
            int key = jbase + c * 16 + r;
            float4 v = make_float4(0.f, 0.f, 0.f, 0.f);
            if (key >= 0 && key < SEQ) {
                if (c4 < NOPE)
                    v = *reinterpret_cast<const float4*>(
                        &g_kv[(size_t)key * KV_W + h * 256 + c4]);
                else
                    v = *reinterpret_cast<const float4*>(
                        &g_krope[(size_t)key * ROPE_D + (c4 - NOPE)]);
            }
            *reinterpret_cast<float4*>(&Ks[r][c4]) = v;
        }
        __syncthreads();
        float acc = 0.0f;
        #pragma unroll
        for (int d = 0; d < QKD; d += 4) {
            float4 qv = *reinterpret_cast<const float4*>(&Qs[q][d]);
            float4 kv = *reinterpret_cast<const float4*>(&Ks[j][d]);
            acc = fmaf(qv.x, kv.x, acc);
            acc = fmaf(qv.y, kv.y, acc);
            acc = fmaf(qv.z, kv.z, acc);
            acc = fmaf(qv.w, kv.w, acc);
        }
        Ls[q][c * 16 + j] = acc;
        __syncthreads();
    }

    {
        const int lane = tid & 31;
        const int wrp  = tid >> 5;
        const float snk = sinks[h];
        #pragma unroll
        for (int rr = 0; rr < 2; rr++) {
            int row = wrp + rr * 8;
            float vals[5];
            float m = NEGINF;
            #pragma unroll
            for (int u = 0; u < 5; u++) {
                int t = lane + u * 32;
                float x = NEGINF;
                if (t < 143 && t >= row && t <= row + 127 && (jbase + t) >= 0)
                    x = Ls[row][t] * ATTN_SCALE;
                vals[u] = x;
                m = fmaxf(m, x);
            }
            #pragma unroll
            for (int o = 16; o > 0; o >>= 1) m = fmaxf(m, __shfl_xor_sync(0xFFFFFFFFu, m, o));
            m = fmaxf(m, snk);
            float s = 0.0f;
            #pragma unroll
            for (int u = 0; u < 5; u++) {
                float p = (vals[u] > 0.5f * NEGINF) ? __expf(vals[u] - m) : 0.0f;
                vals[u] = p;
                s += p;
            }
            #pragma unroll
            for (int o = 16; o > 0; o >>= 1) s += __shfl_xor_sync(0xFFFFFFFFu, s, o);
            float inv = 1.0f / (s + __expf(snk - m));
            #pragma unroll
            for (int u = 0; u < 5; u++) {
                int t = lane + u * 32;
                if (t < LW) Ls[row][t] = vals[u] * inv;
            }
        }
    }
    __syncthreads();

    const int dg = tid & 15;
    float oacc[8];
    #pragma unroll
    for (int e = 0; e < 8; e++) oacc[e] = 0.0f;

    for (int c = 0; c < 9; c++) {
        #pragma unroll
        for (int it = 0; it < 2; it++) {
            int lin = tid + it * 256;
            int r   = lin >> 5;
            int c4  = (lin & 31) * 4;
            int key = jbase + c * 16 + r;
            float4 v = make_float4(0.f, 0.f, 0.f, 0.f);
            if (key >= 0 && key < SEQ)
                v = *reinterpret_cast<const float4*>(
                    &g_kv[(size_t)key * KV_W + h * 256 + NOPE + c4]);
            *reinterpret_cast<float4*>(&Vs[r][c4]) = v;
        }
        __syncthreads();
        #pragma unroll
        for (int r = 0; r < 16; r++) {
            float p = Ls[q][c * 16 + r];
            float4 v0 = *reinterpret_cast<float4*>(&Vs[r][dg * 8]);
            float4 v1 = *reinterpret_cast<float4*>(&Vs[r][dg * 8 + 4]);
            oacc[0] = fmaf(p, v0.x, oacc[0]);
            oacc[1] = fmaf(p, v0.y, oacc[1]);
            oacc[2] = fmaf(p, v0.z, oacc[2]);
            oacc[3] = fmaf(p, v0.w, oacc[3]);
            oacc[4] = fmaf(p, v1.x, oacc[4]);
            oacc[5] = fmaf(p, v1.y, oacc[5]);
            oacc[6] = fmaf(p, v1.z, oacc[6]);
            oacc[7] = fmaf(p, v1.w, oacc[7]);
        }
        __syncthreads();
    }

    // direct fp16 write (same rounding cvt_act used to apply)
    __half ho[8];
    #pragma unroll
    for (int e = 0; e < 8; e++) ho[e] = __float2half_rn(oacc[e]);
    size_t obase = (size_t)(i0 + q) * AOW + h * VD + dg * 8;
    *reinterpret_cast<uint4*>(&g_ah[obase]) = *reinterpret_cast<uint4*>(ho);
}

// ---------------- launch ----------------
extern "C" void kernel_launch(void* const* d_in, const int* in_sizes, int n_in,
                              void* d_out, int out_size)
{
    const float* hidden = (const float*)d_in[0];
    const float* cosp   = (const float*)d_in[1];
    const float* sinp   = (const float*)d_in[2];
    const float* Wq     = (const float*)d_in[3];
    const float* bq     = (const float*)d_in[4];
    const float* Wkva   = (const float*)d_in[5];
    const float* bkva   = (const float*)d_in[6];
    const float* Wkvb   = (const float*)d_in[7];
    const float* Wo     = (const float*)d_in[8];
    const float* bo     = (const float*)d_in[9];
    const float* sinks  = (const float*)d_in[10];
    float* out = (float*)d_out;

    float *q, *ckv, *kv;
    __half *ah, *wqh, *wkvah, *wkvbh, *woh;
    cudaGetSymbolAddress((void**)&q,     g_q);
    cudaGetSymbolAddress((void**)&ckv,   g_ckv);
    cudaGetSymbolAddress((void**)&kv,    g_kv);
    cudaGetSymbolAddress((void**)&ah,    g_ah);
    cudaGetSymbolAddress((void**)&wqh,   g_wqh);
    cudaGetSymbolAddress((void**)&wkvah, g_wkvah);
    cudaGetSymbolAddress((void**)&wkvbh, g_wkvbh);
    cudaGetSymbolAddress((void**)&woh,   g_woh);

    cudaFuncSetAttribute(gemm_h,
                         cudaFuncAttributeMaxDynamicSharedMemorySize, GEMM_SMEM);

    // ---- weight converts ----
    cvt_wgt<<<(size_t)HID * QW / 4 / 256, 256>>>(Wq, wqh);
    cvt_wgt<<<(size_t)HID * CKV_W / 4 / 256, 256>>>(Wkva, wkvah);
    cvt_wgt<<<(size_t)KV_RANK * KV_W / 4 / 256, 256>>>(Wkvb, wkvbh);
    cvt_wgt<<<(size_t)AOW * HID / 4 / 256, 256>>>(Wo, woh);

    // ---- hidden convert, Q and KVA projections ----
    cvt_act<<<SEQ * HID / 4 / 256, 256>>>(hidden, ah, HID, HID);
    gemm_h<<<dim3(QW / 128, SEQ / 128), 256, GEMM_SMEM>>>(
        ah, wqh, bq, q, QW, QW, HID);
    gemm_h<<<dim3((CKV_W + 127) / 128, SEQ / 128), 256, GEMM_SMEM>>>(
        ah, wkvah, bkva, ckv, CKV_W, CKV_W, HID);

    // ---- RoPE ----
    rope_q_kernel<<<(SEQ * NH * 32) / 256, 256>>>(cosp, sinp);
    rope_k_kernel<<<(SEQ * 32) / 256, 256>>>(cosp, sinp);

    // ---- latent convert, KV expansion ----
    cvt_act<<<SEQ * KV_RANK / 4 / 256, 256>>>(ckv, ah, CKV_W, KV_RANK);
    gemm_h<<<dim3(KV_W / 128, SEQ / 128), 256, GEMM_SMEM>>>(
        ah, wkvbh, nullptr, kv, KV_W, KV_W, KV_RANK);

    // ---- attention (query-tiled, writes fp16 into g_ah) ----
    attn_tile_kernel<<<dim3(SEQ / QT, NH), 256>>>(sinks);

    // ---- output projection ----
    gemm_h<<<dim3(HID / 128, SEQ / 128), 256, GEMM_SMEM>>>(
        ah, woh, bo, out, HID, HID, AOW);
}